// round 3
// baseline (speedup 1.0000x reference)
#include <cuda_runtime.h>
#include <cuda_fp16.h>

#define EMB   1024
#define HEADS 16
#define HDIM  64
#define SEQ   2048
#define BATCH 4
#define MTOT  (BATCH * SEQ)   // 8192

// ---------------------------------------------------------------------------
// Scratch
// ---------------------------------------------------------------------------
__device__ float g_q[(size_t)BATCH * HEADS * SEQ * HDIM];
__device__ float g_k[(size_t)BATCH * HEADS * SEQ * HDIM];
__device__ float g_v[(size_t)BATCH * HEADS * SEQ * HDIM];
__device__ float g_o[(size_t)MTOT * EMB];

// ---------------------------------------------------------------------------
// Helpers
// ---------------------------------------------------------------------------
__device__ __forceinline__ unsigned pack_h2(float lo, float hi) {
    __half2 h = __floats2half2_rn(lo, hi);
    return *reinterpret_cast<unsigned*>(&h);
}

__device__ __forceinline__ void ldsm4(unsigned& r0, unsigned& r1, unsigned& r2,
                                      unsigned& r3, const void* p) {
    unsigned addr = (unsigned)__cvta_generic_to_shared(p);
    asm volatile("ldmatrix.sync.aligned.m8n8.x4.shared.b16 {%0,%1,%2,%3},[%4];"
                 : "=r"(r0), "=r"(r1), "=r"(r2), "=r"(r3) : "r"(addr));
}

__device__ __forceinline__ void ldsm4t(unsigned& r0, unsigned& r1, unsigned& r2,
                                       unsigned& r3, const void* p) {
    unsigned addr = (unsigned)__cvta_generic_to_shared(p);
    asm volatile("ldmatrix.sync.aligned.m8n8.x4.trans.shared.b16 {%0,%1,%2,%3},[%4];"
                 : "=r"(r0), "=r"(r1), "=r"(r2), "=r"(r3) : "r"(addr));
}

__device__ __forceinline__ void mma16816(float* d, const unsigned* a, const unsigned* b) {
    asm volatile(
        "mma.sync.aligned.m16n8k16.row.col.f32.f16.f16.f32 "
        "{%0,%1,%2,%3}, {%4,%5,%6,%7}, {%8,%9}, {%0,%1,%2,%3};\n"
        : "+f"(d[0]), "+f"(d[1]), "+f"(d[2]), "+f"(d[3])
        : "r"(a[0]), "r"(a[1]), "r"(a[2]), "r"(a[3]), "r"(b[0]), "r"(b[1]));
}

// ---------------------------------------------------------------------------
// fp16 GEMM:  C = A(MxK) * B(NxK)^T + bias     (fp32 in/out, fp32 accum)
// MODE 0: C[m*N+n].  MODE 1: head-split to [B,H,S,Dh].
// blockIdx.z selects (B, bias, C) -> fused QKV.
// Block tile 128x128, BK=32, 256 threads, 8 warps (2M x 4N), warp 64x32.
// ---------------------------------------------------------------------------
template <int MODE>
__global__ __launch_bounds__(256)
void gemm_f16(const float* __restrict__ A,
              const float* __restrict__ B0, const float* __restrict__ B1,
              const float* __restrict__ B2,
              const float* __restrict__ bi0, const float* __restrict__ bi1,
              const float* __restrict__ bi2,
              float* __restrict__ C0, float* __restrict__ C1, float* __restrict__ C2,
              int M, int N, int K)
{
    const float* B    = (blockIdx.z == 0) ? B0  : (blockIdx.z == 1) ? B1  : B2;
    const float* bias = (blockIdx.z == 0) ? bi0 : (blockIdx.z == 1) ? bi1 : bi2;
    float*       C    = (blockIdx.z == 0) ? C0  : (blockIdx.z == 1) ? C1  : C2;

    __shared__ __half Ah[128][40];   // pad 8 halves -> ldmatrix conflict-free
    __shared__ __half Bh[128][40];

    const int tid  = threadIdx.x;
    const int warp = tid >> 5;
    const int lane = tid & 31;
    const int g = lane >> 2;
    const int q = lane & 3;
    const int wm = (warp >> 2) * 64;
    const int wn = (warp & 3) * 32;
    const int bm = blockIdx.y * 128;
    const int bn = blockIdx.x * 128;

    // staging: thread covers 16 halves of one row
    const int srow = tid & 127;
    const int skh  = (tid >> 7) * 16;

    // ldmatrix lane addressing
    const int arow = (lane & 7) + ((lane >> 3) & 1) * 8;  // A: row within m16
    const int acol = (lane >> 4) * 8;                     // A: col within k16
    const int brow = ((lane >> 4) << 3) + (lane & 7);     // B: row within n16
    const int bcol = ((lane >> 3) & 1) << 3;              // B: col within k16

    float c[4][4][4];
#pragma unroll
    for (int mt = 0; mt < 4; mt++)
#pragma unroll
        for (int nt = 0; nt < 4; nt++)
#pragma unroll
            for (int i = 0; i < 4; i++) c[mt][nt][i] = 0.f;

    for (int k0 = 0; k0 < K; k0 += 32) {
        {
            const float* Ar = &A[(size_t)(bm + srow) * K + k0 + skh];
            const float* Br = &B[(size_t)(bn + srow) * K + k0 + skh];
            float4 a0 = *(const float4*)(Ar + 0);
            float4 a1 = *(const float4*)(Ar + 4);
            float4 a2 = *(const float4*)(Ar + 8);
            float4 a3 = *(const float4*)(Ar + 12);
            float4 b0 = *(const float4*)(Br + 0);
            float4 b1 = *(const float4*)(Br + 4);
            float4 b2 = *(const float4*)(Br + 8);
            float4 b3 = *(const float4*)(Br + 12);
            uint4 pa0 = make_uint4(pack_h2(a0.x, a0.y), pack_h2(a0.z, a0.w),
                                   pack_h2(a1.x, a1.y), pack_h2(a1.z, a1.w));
            uint4 pa1 = make_uint4(pack_h2(a2.x, a2.y), pack_h2(a2.z, a2.w),
                                   pack_h2(a3.x, a3.y), pack_h2(a3.z, a3.w));
            uint4 pb0 = make_uint4(pack_h2(b0.x, b0.y), pack_h2(b0.z, b0.w),
                                   pack_h2(b1.x, b1.y), pack_h2(b1.z, b1.w));
            uint4 pb1 = make_uint4(pack_h2(b2.x, b2.y), pack_h2(b2.z, b2.w),
                                   pack_h2(b3.x, b3.y), pack_h2(b3.z, b3.w));
            *(uint4*)&Ah[srow][skh]     = pa0;
            *(uint4*)&Ah[srow][skh + 8] = pa1;
            *(uint4*)&Bh[srow][skh]     = pb0;
            *(uint4*)&Bh[srow][skh + 8] = pb1;
        }
        __syncthreads();

#pragma unroll
        for (int ks = 0; ks < 2; ks++) {
            unsigned a[4][4], b[4][2];
#pragma unroll
            for (int mt = 0; mt < 4; mt++)
                ldsm4(a[mt][0], a[mt][1], a[mt][2], a[mt][3],
                      &Ah[wm + mt * 16 + arow][ks * 16 + acol]);
#pragma unroll
            for (int jp = 0; jp < 2; jp++) {
                unsigned r0, r1, r2, r3;
                ldsm4(r0, r1, r2, r3, &Bh[wn + jp * 16 + brow][ks * 16 + bcol]);
                b[2 * jp][0] = r0; b[2 * jp][1] = r1;
                b[2 * jp + 1][0] = r2; b[2 * jp + 1][1] = r3;
            }
#pragma unroll
            for (int mt = 0; mt < 4; mt++)
#pragma unroll
                for (int nt = 0; nt < 4; nt++)
                    mma16816(c[mt][nt], a[mt], b[nt]);
        }
        __syncthreads();
    }

#pragma unroll
    for (int mt = 0; mt < 4; mt++) {
        const int r0 = bm + wm + mt * 16 + g;
        const int r1 = r0 + 8;
#pragma unroll
        for (int nt = 0; nt < 4; nt++) {
            const int n0 = bn + wn + nt * 8 + 2 * q;
            const float b0 = bias[n0];
            const float b1 = bias[n0 + 1];
            float2 v0 = make_float2(c[mt][nt][0] + b0, c[mt][nt][1] + b1);
            float2 v1 = make_float2(c[mt][nt][2] + b0, c[mt][nt][3] + b1);
            if (MODE == 0) {
                *(float2*)&C[(size_t)r0 * N + n0] = v0;
                *(float2*)&C[(size_t)r1 * N + n0] = v1;
            } else {
                const int h = n0 >> 6, d = n0 & 63;
                const int bb0 = r0 >> 11, s0 = r0 & 2047;
                const int bb1 = r1 >> 11, s1 = r1 & 2047;
                *(float2*)&C[(((size_t)(bb0 * HEADS + h)) * SEQ + s0) * HDIM + d] = v0;
                *(float2*)&C[(((size_t)(bb1 * HEADS + h)) * SEQ + s1) * HDIM + d] = v1;
            }
        }
    }
}

// ---------------------------------------------------------------------------
// fp16 flash attention. Grid (SEQ/64, B*H), 128 threads (4 warps x 16 rows).
// K/V tiles of 64 keys in smem (half, ldmatrix layouts). S->P frags register-
// resident (C-frag == A-frag layout for m16n8k16).
// ---------------------------------------------------------------------------
__global__ __launch_bounds__(128)
void attn_f16(const float* __restrict__ Q, const float* __restrict__ K,
              const float* __restrict__ V, float* __restrict__ O)
{
    __shared__ __half Kh[64][72];   // pad 8 -> ldmatrix conflict-free
    __shared__ __half Vh[64][72];

    const int bh   = blockIdx.y;
    const int q0   = blockIdx.x * 64;
    const int tid  = threadIdx.x;
    const int warp = tid >> 5;
    const int lane = tid & 31;
    const int g = lane >> 2;
    const int q = lane & 3;
    const float scale = 1.0f / 32.0f;   // 1/sqrt(EMB)

    const float* Qg = Q + ((size_t)bh * SEQ + q0) * HDIM;
    const float* Kg = K + (size_t)bh * SEQ * HDIM;
    const float* Vg = V + (size_t)bh * SEQ * HDIM;

    const int srow = tid >> 1;
    const int sc   = (tid & 1) * 32;

    // ldmatrix lane addressing
    const int arow = (lane & 7) + ((lane >> 3) & 1) * 8;
    const int acol = (lane >> 4) * 8;
    const int brow = ((lane >> 4) << 3) + (lane & 7);
    const int bcol = ((lane >> 3) & 1) << 3;
    const int vrow = (lane & 7) + (((lane >> 3) & 1) << 3);
    const int vcol = (lane >> 4) << 3;

    // ---- Stage Q (scaled) through Kh, pull A-frags ----
    {
        const float* Qr = &Qg[(size_t)srow * HDIM + sc];
#pragma unroll
        for (int ii = 0; ii < 4; ii++) {
            float4 f0 = *(const float4*)(Qr + ii * 8);
            float4 f1 = *(const float4*)(Qr + ii * 8 + 4);
            uint4 p = make_uint4(pack_h2(f0.x * scale, f0.y * scale),
                                 pack_h2(f0.z * scale, f0.w * scale),
                                 pack_h2(f1.x * scale, f1.y * scale),
                                 pack_h2(f1.z * scale, f1.w * scale));
            *(uint4*)&Kh[srow][sc + ii * 8] = p;
        }
    }
    __syncthreads();

    unsigned qa[4][4];
#pragma unroll
    for (int ks = 0; ks < 4; ks++)
        ldsm4(qa[ks][0], qa[ks][1], qa[ks][2], qa[ks][3],
              &Kh[warp * 16 + arow][ks * 16 + acol]);
    __syncthreads();

    float o[8][4];
#pragma unroll
    for (int nt = 0; nt < 8; nt++)
#pragma unroll
        for (int i = 0; i < 4; i++) o[nt][i] = 0.f;
    float m0 = -1e30f, m1 = -1e30f, l0 = 0.f, l1 = 0.f;

    for (int kt = 0; kt < SEQ; kt += 64) {
        // ---- Stage K,V (fp16) ----
        {
            const float* Kr = &Kg[(size_t)(kt + srow) * HDIM + sc];
            const float* Vr = &Vg[(size_t)(kt + srow) * HDIM + sc];
#pragma unroll
            for (int ii = 0; ii < 4; ii++) {
                float4 f0 = *(const float4*)(Kr + ii * 8);
                float4 f1 = *(const float4*)(Kr + ii * 8 + 4);
                *(uint4*)&Kh[srow][sc + ii * 8] =
                    make_uint4(pack_h2(f0.x, f0.y), pack_h2(f0.z, f0.w),
                               pack_h2(f1.x, f1.y), pack_h2(f1.z, f1.w));
                float4 v0 = *(const float4*)(Vr + ii * 8);
                float4 v1 = *(const float4*)(Vr + ii * 8 + 4);
                *(uint4*)&Vh[srow][sc + ii * 8] =
                    make_uint4(pack_h2(v0.x, v0.y), pack_h2(v0.z, v0.w),
                               pack_h2(v1.x, v1.y), pack_h2(v1.z, v1.w));
            }
        }
        __syncthreads();

        // ---- S = Q K^T ----
        float s[8][4];
#pragma unroll
        for (int nt = 0; nt < 8; nt++) {
            s[nt][0] = 0.f; s[nt][1] = 0.f; s[nt][2] = 0.f; s[nt][3] = 0.f;
        }
#pragma unroll
        for (int ks = 0; ks < 4; ks++) {
#pragma unroll
            for (int jp = 0; jp < 4; jp++) {
                unsigned r0, r1, r2, r3;
                ldsm4(r0, r1, r2, r3, &Kh[jp * 16 + brow][ks * 16 + bcol]);
                unsigned b0[2] = {r0, r1}, b1[2] = {r2, r3};
                mma16816(s[2 * jp], qa[ks], b0);
                mma16816(s[2 * jp + 1], qa[ks], b1);
            }
        }

        // ---- Online softmax ----
        float mx0 = -1e30f, mx1 = -1e30f;
#pragma unroll
        for (int nt = 0; nt < 8; nt++) {
            mx0 = fmaxf(mx0, fmaxf(s[nt][0], s[nt][1]));
            mx1 = fmaxf(mx1, fmaxf(s[nt][2], s[nt][3]));
        }
        mx0 = fmaxf(mx0, __shfl_xor_sync(0xffffffffu, mx0, 1));
        mx0 = fmaxf(mx0, __shfl_xor_sync(0xffffffffu, mx0, 2));
        mx1 = fmaxf(mx1, __shfl_xor_sync(0xffffffffu, mx1, 1));
        mx1 = fmaxf(mx1, __shfl_xor_sync(0xffffffffu, mx1, 2));

        const float nm0 = fmaxf(m0, mx0);
        const float nm1 = fmaxf(m1, mx1);
        const float cor0 = __expf(m0 - nm0);
        const float cor1 = __expf(m1 - nm1);
        m0 = nm0; m1 = nm1;

        float sum0 = 0.f, sum1 = 0.f;
#pragma unroll
        for (int nt = 0; nt < 8; nt++) {
            s[nt][0] = __expf(s[nt][0] - m0);
            s[nt][1] = __expf(s[nt][1] - m0);
            s[nt][2] = __expf(s[nt][2] - m1);
            s[nt][3] = __expf(s[nt][3] - m1);
            sum0 += s[nt][0] + s[nt][1];
            sum1 += s[nt][2] + s[nt][3];
        }
        sum0 += __shfl_xor_sync(0xffffffffu, sum0, 1);
        sum0 += __shfl_xor_sync(0xffffffffu, sum0, 2);
        sum1 += __shfl_xor_sync(0xffffffffu, sum1, 1);
        sum1 += __shfl_xor_sync(0xffffffffu, sum1, 2);
        l0 = l0 * cor0 + sum0;
        l1 = l1 * cor1 + sum1;

#pragma unroll
        for (int nt = 0; nt < 8; nt++) {
            o[nt][0] *= cor0; o[nt][1] *= cor0;
            o[nt][2] *= cor1; o[nt][3] *= cor1;
        }

        // ---- O += P V  (P A-frags from S C-frags, zero shuffles) ----
#pragma unroll
        for (int kg = 0; kg < 4; kg++) {
            unsigned a[4];
            a[0] = pack_h2(s[2 * kg][0],     s[2 * kg][1]);
            a[1] = pack_h2(s[2 * kg][2],     s[2 * kg][3]);
            a[2] = pack_h2(s[2 * kg + 1][0], s[2 * kg + 1][1]);
            a[3] = pack_h2(s[2 * kg + 1][2], s[2 * kg + 1][3]);
#pragma unroll
            for (int dp = 0; dp < 4; dp++) {
                unsigned r0, r1, r2, r3;
                ldsm4t(r0, r1, r2, r3, &Vh[kg * 16 + vrow][dp * 16 + vcol]);
                unsigned b0[2] = {r0, r1}, b1[2] = {r2, r3};
                mma16816(o[2 * dp], a, b0);
                mma16816(o[2 * dp + 1], a, b1);
            }
        }
        __syncthreads();
    }

    // ---- Epilogue ----
    const float inv0 = 1.0f / l0;
    const float inv1 = 1.0f / l1;
    const int b = bh >> 4;
    const int h = bh & 15;
    const int r0 = q0 + warp * 16 + g;
    const int r1 = r0 + 8;
#pragma unroll
    for (int nt = 0; nt < 8; nt++) {
        const int col = h * HDIM + nt * 8 + 2 * q;
        *(float2*)&O[((size_t)(b * SEQ + r0)) * EMB + col] =
            make_float2(o[nt][0] * inv0, o[nt][1] * inv0);
        *(float2*)&O[((size_t)(b * SEQ + r1)) * EMB + col] =
            make_float2(o[nt][2] * inv1, o[nt][3] * inv1);
    }
}

// ---------------------------------------------------------------------------
// Launch
// ---------------------------------------------------------------------------
extern "C" void kernel_launch(void* const* d_in, const int* in_sizes, int n_in,
                              void* d_out, int out_size)
{
    const float* x  = (const float*)d_in[0];
    const float* Wq = (const float*)d_in[1];
    const float* bq = (const float*)d_in[2];
    const float* Wk = (const float*)d_in[3];
    const float* bk = (const float*)d_in[4];
    const float* Wv = (const float*)d_in[5];
    const float* bv = (const float*)d_in[6];
    const float* Wo = (const float*)d_in[7];
    const float* bo = (const float*)d_in[8];
    float* out = (float*)d_out;

    float *dq, *dk, *dv, *doo;
    cudaGetSymbolAddress((void**)&dq,  g_q);
    cudaGetSymbolAddress((void**)&dk,  g_k);
    cudaGetSymbolAddress((void**)&dv,  g_v);
    cudaGetSymbolAddress((void**)&doo, g_o);

    dim3 qkv_grid(EMB / 128, MTOT / 128, 3);   // fused QKV
    gemm_f16<1><<<qkv_grid, 256>>>(x, Wq, Wk, Wv, bq, bk, bv, dq, dk, dv,
                                   MTOT, EMB, EMB);

    dim3 agrid(SEQ / 64, BATCH * HEADS);       // (32, 64)
    attn_f16<<<agrid, 128>>>(dq, dk, dv, doo);

    dim3 ogrid(EMB / 128, MTOT / 128, 1);
    gemm_f16<0><<<ogrid, 256>>>(doo, Wo, Wo, Wo, bo, bo, bo, out, out, out,
                                MTOT, EMB, EMB);
}

// round 4
// speedup vs baseline: 3.2875x; 3.2875x over previous
#include <cuda_runtime.h>
#include <cuda_fp16.h>

#define EMB   1024
#define HEADS 16
#define HDIM  64
#define SEQ   2048
#define BATCH 4
#define MTOT  (BATCH * SEQ)   // 8192

// ---------------------------------------------------------------------------
// Scratch (fp16 everywhere between kernels)
// ---------------------------------------------------------------------------
__device__ __half g_hx[(size_t)MTOT * EMB];                    // x in fp16
__device__ __half g_hwq[(size_t)EMB * EMB];                    // Wq * (1/32)
__device__ __half g_hwk[(size_t)EMB * EMB];
__device__ __half g_hwv[(size_t)EMB * EMB];
__device__ __half g_hwo[(size_t)EMB * EMB];
__device__ __half g_qh[(size_t)BATCH * HEADS * SEQ * HDIM];    // [B,H,S,Dh]
__device__ __half g_kh[(size_t)BATCH * HEADS * SEQ * HDIM];
__device__ __half g_vh[(size_t)BATCH * HEADS * SEQ * HDIM];
__device__ __half g_oh[(size_t)MTOT * EMB];                    // attn out fp16

// ---------------------------------------------------------------------------
// Helpers
// ---------------------------------------------------------------------------
__device__ __forceinline__ unsigned pack_h2(float lo, float hi) {
    __half2 h = __floats2half2_rn(lo, hi);
    return *reinterpret_cast<unsigned*>(&h);
}

__device__ __forceinline__ void cpa16(const void* smem, const void* gmem) {
    unsigned a = (unsigned)__cvta_generic_to_shared(smem);
    asm volatile("cp.async.cg.shared.global [%0],[%1],16;\n" :: "r"(a), "l"(gmem));
}
#define CP_COMMIT() asm volatile("cp.async.commit_group;\n")
#define CP_WAIT(N)  asm volatile("cp.async.wait_group %0;\n" :: "n"(N))

__device__ __forceinline__ void ldsm4(unsigned& r0, unsigned& r1, unsigned& r2,
                                      unsigned& r3, const void* p) {
    unsigned addr = (unsigned)__cvta_generic_to_shared(p);
    asm volatile("ldmatrix.sync.aligned.m8n8.x4.shared.b16 {%0,%1,%2,%3},[%4];"
                 : "=r"(r0), "=r"(r1), "=r"(r2), "=r"(r3) : "r"(addr));
}
__device__ __forceinline__ void ldsm4t(unsigned& r0, unsigned& r1, unsigned& r2,
                                       unsigned& r3, const void* p) {
    unsigned addr = (unsigned)__cvta_generic_to_shared(p);
    asm volatile("ldmatrix.sync.aligned.m8n8.x4.trans.shared.b16 {%0,%1,%2,%3},[%4];"
                 : "=r"(r0), "=r"(r1), "=r"(r2), "=r"(r3) : "r"(addr));
}
__device__ __forceinline__ void mma16816(float* d, const unsigned* a, const unsigned* b) {
    asm volatile(
        "mma.sync.aligned.m16n8k16.row.col.f32.f16.f16.f32 "
        "{%0,%1,%2,%3}, {%4,%5,%6,%7}, {%8,%9}, {%0,%1,%2,%3};\n"
        : "+f"(d[0]), "+f"(d[1]), "+f"(d[2]), "+f"(d[3])
        : "r"(a[0]), "r"(a[1]), "r"(a[2]), "r"(a[3]), "r"(b[0]), "r"(b[1]));
}

// Swizzled smem offset for a 16B chunk: rows of 64 halves (128B), 8 chunks/row.
__device__ __forceinline__ int swz(int row, int c) {
    return (row * 8 + (c ^ (row & 7))) * 8;   // in halves
}

// ---------------------------------------------------------------------------
// fp32 -> fp16 conversion (optionally scaled)
// ---------------------------------------------------------------------------
__global__ void cvt_f2h(const float* __restrict__ s, __half* __restrict__ d,
                        int n4, float scale)
{
    int i = blockIdx.x * blockDim.x + threadIdx.x;
    if (i < n4) {
        float4 f = ((const float4*)s)[i];
        uint2 p;
        p.x = pack_h2(f.x * scale, f.y * scale);
        p.y = pack_h2(f.z * scale, f.w * scale);
        ((uint2*)d)[i] = p;
    }
}

// ---------------------------------------------------------------------------
// HGEMM: C = A(MxK) * B(NxK)^T + bias*bs     (half in, fp32 accum)
// MODE 0: C fp32 [m*N+n].  MODE 1: C fp16 head-split [B,H,S,Dh].
// blockIdx.z selects weight/bias/output (fused QKV).
// 128x128x64 tiles, 256 threads (8 warps 2Mx4N, warp 64x32), cp.async DB.
// Dynamic smem: 2 stages * (A 16KB + B 16KB) = 64KB.
// ---------------------------------------------------------------------------
template <int MODE>
__global__ __launch_bounds__(256)
void hgemm(const __half* __restrict__ A,
           const __half* __restrict__ B0, const __half* __restrict__ B1,
           const __half* __restrict__ B2,
           const float* __restrict__ bi0, const float* __restrict__ bi1,
           const float* __restrict__ bi2, float bs0, float bs1, float bs2,
           void* C0v, void* C1v, void* C2v, int M, int N, int K)
{
    extern __shared__ __half dynsm[];
    __half* sA[2] = {dynsm, dynsm + 2 * 128 * 64};
    __half* sB[2] = {dynsm + 128 * 64, dynsm + 3 * 128 * 64};

    const int z = blockIdx.z;
    const __half* B    = (z == 0) ? B0  : (z == 1) ? B1  : B2;
    const float*  bias = (z == 0) ? bi0 : (z == 1) ? bi1 : bi2;
    const float   bs   = (z == 0) ? bs0 : (z == 1) ? bs1 : bs2;
    void* Cv           = (z == 0) ? C0v : (z == 1) ? C1v : C2v;

    const int tid  = threadIdx.x;
    const int warp = tid >> 5;
    const int lane = tid & 31;
    const int g = lane >> 2;
    const int q = lane & 3;
    const int wm = (warp >> 2) * 64;
    const int wn = (warp & 3) * 32;
    const int bm = blockIdx.y * 128;
    const int bn = blockIdx.x * 128;

    const int arow = (lane & 7) + ((lane >> 3) & 1) * 8;
    const int acol = (lane >> 4) * 8;
    const int brow = ((lane >> 4) << 3) + (lane & 7);
    const int bcol = ((lane >> 3) & 1) << 3;

    const __half* Ag = A + (size_t)bm * K;
    const __half* Bg = B + (size_t)bn * K;

    const int srow = tid >> 3;        // 0..31 per 256-thread pass -> 4 passes
    const int sch  = tid & 7;

    float c[4][4][4];
#pragma unroll
    for (int mt = 0; mt < 4; mt++)
#pragma unroll
        for (int nt = 0; nt < 4; nt++)
#pragma unroll
            for (int i = 0; i < 4; i++) c[mt][nt][i] = 0.f;

    const int NIT = K >> 6;

    // prologue stage 0
#pragma unroll
    for (int i = 0; i < 4; i++) {
        const int row = srow + i * 32;
        cpa16(&sA[0][swz(row, sch)], Ag + (size_t)row * K + sch * 8);
        cpa16(&sB[0][swz(row, sch)], Bg + (size_t)row * K + sch * 8);
    }
    CP_COMMIT();

    for (int it = 0; it < NIT; it++) {
        if (it + 1 < NIT) {
            const int nb = (it + 1) & 1;
            const int k0 = (it + 1) << 6;
#pragma unroll
            for (int i = 0; i < 4; i++) {
                const int row = srow + i * 32;
                cpa16(&sA[nb][swz(row, sch)], Ag + (size_t)row * K + k0 + sch * 8);
                cpa16(&sB[nb][swz(row, sch)], Bg + (size_t)row * K + k0 + sch * 8);
            }
            CP_COMMIT();
            CP_WAIT(1);
        } else {
            CP_WAIT(0);
        }
        __syncthreads();

        const __half* bA = sA[it & 1];
        const __half* bB = sB[it & 1];
#pragma unroll
        for (int ks = 0; ks < 4; ks++) {
            unsigned a[4][4], b[4][2];
#pragma unroll
            for (int mt = 0; mt < 4; mt++) {
                const int row = wm + mt * 16 + arow;
                ldsm4(a[mt][0], a[mt][1], a[mt][2], a[mt][3],
                      &bA[swz(row, ks * 2 + (acol >> 3))]);
            }
#pragma unroll
            for (int jp = 0; jp < 2; jp++) {
                const int row = wn + jp * 16 + brow;
                unsigned r0, r1, r2, r3;
                ldsm4(r0, r1, r2, r3, &bB[swz(row, ks * 2 + (bcol >> 3))]);
                b[2 * jp][0] = r0; b[2 * jp][1] = r1;
                b[2 * jp + 1][0] = r2; b[2 * jp + 1][1] = r3;
            }
#pragma unroll
            for (int mt = 0; mt < 4; mt++)
#pragma unroll
                for (int nt = 0; nt < 4; nt++)
                    mma16816(c[mt][nt], a[mt], b[nt]);
        }
        __syncthreads();
    }

    // Epilogue
#pragma unroll
    for (int mt = 0; mt < 4; mt++) {
        const int r0 = bm + wm + mt * 16 + g;
        const int r1 = r0 + 8;
#pragma unroll
        for (int nt = 0; nt < 4; nt++) {
            const int n0 = bn + wn + nt * 8 + 2 * q;
            const float b0f = bias[n0] * bs;
            const float b1f = bias[n0 + 1] * bs;
            if (MODE == 0) {
                float* C = (float*)Cv;
                *(float2*)&C[(size_t)r0 * N + n0] =
                    make_float2(c[mt][nt][0] + b0f, c[mt][nt][1] + b1f);
                *(float2*)&C[(size_t)r1 * N + n0] =
                    make_float2(c[mt][nt][2] + b0f, c[mt][nt][3] + b1f);
            } else {
                __half* C = (__half*)Cv;
                const int h = n0 >> 6, d = n0 & 63;
                const int bb0 = r0 >> 11, s0 = r0 & 2047;
                const int bb1 = r1 >> 11, s1 = r1 & 2047;
                *(unsigned*)&C[(((size_t)(bb0 * HEADS + h)) * SEQ + s0) * HDIM + d] =
                    pack_h2(c[mt][nt][0] + b0f, c[mt][nt][1] + b1f);
                *(unsigned*)&C[(((size_t)(bb1 * HEADS + h)) * SEQ + s1) * HDIM + d] =
                    pack_h2(c[mt][nt][2] + b0f, c[mt][nt][3] + b1f);
            }
        }
    }
}

// ---------------------------------------------------------------------------
// fp16 flash attention, cp.async double-buffered K/V.
// Grid (SEQ/64, B*H), 128 threads (4 warps x 16 query rows).
// Q pre-scaled by 1/32 (folded into Wq). All smem rows 64 halves, XOR swizzle.
// ---------------------------------------------------------------------------
__global__ __launch_bounds__(128)
void attn_h(const __half* __restrict__ Q, const __half* __restrict__ K,
            const __half* __restrict__ V, __half* __restrict__ O)
{
    __shared__ __half Qs[64 * 64];
    __shared__ __half Ksm[2][64 * 64];
    __shared__ __half Vsm[2][64 * 64];

    const int bh   = blockIdx.y;
    const int q0   = blockIdx.x * 64;
    const int tid  = threadIdx.x;
    const int warp = tid >> 5;
    const int lane = tid & 31;
    const int g = lane >> 2;
    const int q = lane & 3;

    const __half* Qg = Q + ((size_t)bh * SEQ + q0) * HDIM;
    const __half* Kg = K + (size_t)bh * SEQ * HDIM;
    const __half* Vg = V + (size_t)bh * SEQ * HDIM;

    const int arow = (lane & 7) + ((lane >> 3) & 1) * 8;
    const int acol = (lane >> 4) * 8;
    const int brow = ((lane >> 4) << 3) + (lane & 7);
    const int bcol = ((lane >> 3) & 1) << 3;
    const int vrow = (lane & 7) + (((lane >> 3) & 1) << 3);
    const int vcol = (lane >> 4) << 3;

    const int srow = tid >> 3;     // 0..15 per 128-thread pass -> 4 passes
    const int sch  = tid & 7;

    // Group 0: Q
#pragma unroll
    for (int i = 0; i < 4; i++) {
        const int row = srow + i * 16;
        cpa16(&Qs[swz(row, sch)], Qg + row * HDIM + sch * 8);
    }
    CP_COMMIT();
    // Group 1: K/V tile 0
#pragma unroll
    for (int i = 0; i < 4; i++) {
        const int row = srow + i * 16;
        cpa16(&Ksm[0][swz(row, sch)], Kg + (size_t)row * HDIM + sch * 8);
        cpa16(&Vsm[0][swz(row, sch)], Vg + (size_t)row * HDIM + sch * 8);
    }
    CP_COMMIT();

    CP_WAIT(1);           // Q ready (KV0 may still be in flight)
    __syncthreads();

    unsigned qa[4][4];
#pragma unroll
    for (int ks = 0; ks < 4; ks++) {
        const int row = warp * 16 + arow;
        ldsm4(qa[ks][0], qa[ks][1], qa[ks][2], qa[ks][3],
              &Qs[swz(row, ks * 2 + (acol >> 3))]);
    }

    float o[8][4];
#pragma unroll
    for (int nt = 0; nt < 8; nt++)
#pragma unroll
        for (int i = 0; i < 4; i++) o[nt][i] = 0.f;
    float m0 = -1e30f, m1 = -1e30f, l0 = 0.f, l1 = 0.f;

    const int NT = SEQ / 64;   // 32
    for (int it = 0; it < NT; it++) {
        if (it + 1 < NT) {
            const int nb = (it + 1) & 1;
            const size_t kt = (size_t)(it + 1) * 64;
#pragma unroll
            for (int i = 0; i < 4; i++) {
                const int row = srow + i * 16;
                cpa16(&Ksm[nb][swz(row, sch)], Kg + (kt + row) * HDIM + sch * 8);
                cpa16(&Vsm[nb][swz(row, sch)], Vg + (kt + row) * HDIM + sch * 8);
            }
            CP_COMMIT();
            CP_WAIT(1);
        } else {
            CP_WAIT(0);
        }
        __syncthreads();

        const __half* Kb = Ksm[it & 1];
        const __half* Vb = Vsm[it & 1];

        // ---- S = Q K^T ----
        float s[8][4];
#pragma unroll
        for (int nt = 0; nt < 8; nt++) {
            s[nt][0] = 0.f; s[nt][1] = 0.f; s[nt][2] = 0.f; s[nt][3] = 0.f;
        }
#pragma unroll
        for (int ks = 0; ks < 4; ks++) {
#pragma unroll
            for (int jp = 0; jp < 4; jp++) {
                const int row = jp * 16 + brow;
                unsigned r0, r1, r2, r3;
                ldsm4(r0, r1, r2, r3, &Kb[swz(row, ks * 2 + (bcol >> 3))]);
                unsigned b0[2] = {r0, r1}, b1[2] = {r2, r3};
                mma16816(s[2 * jp], qa[ks], b0);
                mma16816(s[2 * jp + 1], qa[ks], b1);
            }
        }

        // ---- Online softmax ----
        float mx0 = -1e30f, mx1 = -1e30f;
#pragma unroll
        for (int nt = 0; nt < 8; nt++) {
            mx0 = fmaxf(mx0, fmaxf(s[nt][0], s[nt][1]));
            mx1 = fmaxf(mx1, fmaxf(s[nt][2], s[nt][3]));
        }
        mx0 = fmaxf(mx0, __shfl_xor_sync(0xffffffffu, mx0, 1));
        mx0 = fmaxf(mx0, __shfl_xor_sync(0xffffffffu, mx0, 2));
        mx1 = fmaxf(mx1, __shfl_xor_sync(0xffffffffu, mx1, 1));
        mx1 = fmaxf(mx1, __shfl_xor_sync(0xffffffffu, mx1, 2));

        const float nm0 = fmaxf(m0, mx0);
        const float nm1 = fmaxf(m1, mx1);
        const float cor0 = __expf(m0 - nm0);
        const float cor1 = __expf(m1 - nm1);
        m0 = nm0; m1 = nm1;

        float sum0 = 0.f, sum1 = 0.f;
#pragma unroll
        for (int nt = 0; nt < 8; nt++) {
            s[nt][0] = __expf(s[nt][0] - m0);
            s[nt][1] = __expf(s[nt][1] - m0);
            s[nt][2] = __expf(s[nt][2] - m1);
            s[nt][3] = __expf(s[nt][3] - m1);
            sum0 += s[nt][0] + s[nt][1];
            sum1 += s[nt][2] + s[nt][3];
        }
        sum0 += __shfl_xor_sync(0xffffffffu, sum0, 1);
        sum0 += __shfl_xor_sync(0xffffffffu, sum0, 2);
        sum1 += __shfl_xor_sync(0xffffffffu, sum1, 1);
        sum1 += __shfl_xor_sync(0xffffffffu, sum1, 2);
        l0 = l0 * cor0 + sum0;
        l1 = l1 * cor1 + sum1;

#pragma unroll
        for (int nt = 0; nt < 8; nt++) {
            o[nt][0] *= cor0; o[nt][1] *= cor0;
            o[nt][2] *= cor1; o[nt][3] *= cor1;
        }

        // ---- O += P V ----
#pragma unroll
        for (int kg = 0; kg < 4; kg++) {
            unsigned a[4];
            a[0] = pack_h2(s[2 * kg][0],     s[2 * kg][1]);
            a[1] = pack_h2(s[2 * kg][2],     s[2 * kg][3]);
            a[2] = pack_h2(s[2 * kg + 1][0], s[2 * kg + 1][1]);
            a[3] = pack_h2(s[2 * kg + 1][2], s[2 * kg + 1][3]);
#pragma unroll
            for (int dp = 0; dp < 4; dp++) {
                const int row = kg * 16 + vrow;
                unsigned r0, r1, r2, r3;
                ldsm4t(r0, r1, r2, r3, &Vb[swz(row, dp * 2 + (vcol >> 3))]);
                unsigned b0[2] = {r0, r1}, b1[2] = {r2, r3};
                mma16816(o[2 * dp], a, b0);
                mma16816(o[2 * dp + 1], a, b1);
            }
        }
        __syncthreads();
    }

    // ---- Epilogue (fp16 out, [B*S, E] with head offset) ----
    const float inv0 = 1.0f / l0;
    const float inv1 = 1.0f / l1;
    const int b = bh >> 4;
    const int h = bh & 15;
    const int r0 = q0 + warp * 16 + g;
    const int r1 = r0 + 8;
#pragma unroll
    for (int nt = 0; nt < 8; nt++) {
        const int col = h * HDIM + nt * 8 + 2 * q;
        *(unsigned*)&O[((size_t)(b * SEQ + r0)) * EMB + col] =
            pack_h2(o[nt][0] * inv0, o[nt][1] * inv0);
        *(unsigned*)&O[((size_t)(b * SEQ + r1)) * EMB + col] =
            pack_h2(o[nt][2] * inv1, o[nt][3] * inv1);
    }
}

// ---------------------------------------------------------------------------
// Launch
// ---------------------------------------------------------------------------
extern "C" void kernel_launch(void* const* d_in, const int* in_sizes, int n_in,
                              void* d_out, int out_size)
{
    const float* x  = (const float*)d_in[0];
    const float* Wq = (const float*)d_in[1];
    const float* bq = (const float*)d_in[2];
    const float* Wk = (const float*)d_in[3];
    const float* bk = (const float*)d_in[4];
    const float* Wv = (const float*)d_in[5];
    const float* bv = (const float*)d_in[6];
    const float* Wo = (const float*)d_in[7];
    const float* bo = (const float*)d_in[8];
    float* out = (float*)d_out;

    __half *hx, *hwq, *hwk, *hwv, *hwo, *qh, *kh, *vh, *oh;
    cudaGetSymbolAddress((void**)&hx,  g_hx);
    cudaGetSymbolAddress((void**)&hwq, g_hwq);
    cudaGetSymbolAddress((void**)&hwk, g_hwk);
    cudaGetSymbolAddress((void**)&hwv, g_hwv);
    cudaGetSymbolAddress((void**)&hwo, g_hwo);
    cudaGetSymbolAddress((void**)&qh,  g_qh);
    cudaGetSymbolAddress((void**)&kh,  g_kh);
    cudaGetSymbolAddress((void**)&vh,  g_vh);
    cudaGetSymbolAddress((void**)&oh,  g_oh);

    cudaFuncSetAttribute(hgemm<1>, cudaFuncAttributeMaxDynamicSharedMemorySize, 65536);
    cudaFuncSetAttribute(hgemm<0>, cudaFuncAttributeMaxDynamicSharedMemorySize, 65536);

    const float qscale = 1.0f / 32.0f;   // 1/sqrt(EMB), exact power of 2

    // fp32 -> fp16 conversions (scale folded into Wq)
    const int nx4 = MTOT * EMB / 4;      // 2097152
    const int nw4 = EMB * EMB / 4;       // 262144
    cvt_f2h<<<nx4 / 256, 256>>>(x,  hx,  nx4, 1.0f);
    cvt_f2h<<<nw4 / 256, 256>>>(Wq, hwq, nw4, qscale);
    cvt_f2h<<<nw4 / 256, 256>>>(Wk, hwk, nw4, 1.0f);
    cvt_f2h<<<nw4 / 256, 256>>>(Wv, hwv, nw4, 1.0f);
    cvt_f2h<<<nw4 / 256, 256>>>(Wo, hwo, nw4, 1.0f);

    // Fused QKV projection (fp16 head-split outputs; q pre-scaled)
    dim3 qkv_grid(EMB / 128, MTOT / 128, 3);
    hgemm<1><<<qkv_grid, 256, 65536>>>(hx, hwq, hwk, hwv, bq, bk, bv,
                                       qscale, 1.0f, 1.0f,
                                       qh, kh, vh, MTOT, EMB, EMB);

    // Attention
    dim3 agrid(SEQ / 64, BATCH * HEADS);
    attn_h<<<agrid, 128>>>(qh, kh, vh, oh);

    // Output projection (fp32 out)
    dim3 ogrid(EMB / 128, MTOT / 128, 1);
    hgemm<0><<<ogrid, 256, 65536>>>(oh, hwo, hwo, hwo, bo, bo, bo,
                                    1.0f, 1.0f, 1.0f,
                                    out, out, out, MTOT, EMB, EMB);
}